// round 5
// baseline (speedup 1.0000x reference)
#include <cuda_runtime.h>
#include <cstdint>

// Problem constants
#define Bx 256
#define Tx 3000
#define Ix 40
#define Hx 64
#define Gx 256        // 4*H gates
#define RCH 4         // recurrent x_proj chunk steps (3000 % 4 == 0 -> 750 chunks)
#define XTK 50        // xproj tokens per block (3000 % 50 == 0)

// Scratch (allocation-free rule: __device__ globals)
__device__ float g_h[2][(size_t)Bx * Tx * Hx];    // per-direction hidden outputs
__device__ float g_xp[2][(size_t)Bx * Tx * Gx];   // input projections (+biases); dir1 time-reversed

// ---------- packed f32x2 helpers ----------
union F2U { float2 f; unsigned long long u; };

__device__ __forceinline__ void ffma2(unsigned long long& acc,
                                      unsigned long long a,
                                      unsigned long long b) {
    asm("fma.rn.f32x2 %0, %1, %2, %0;" : "+l"(acc) : "l"(a), "l"(b));
}
__device__ __forceinline__ unsigned long long fadd2(unsigned long long a, unsigned long long b) {
    unsigned long long r;
    asm("add.rn.f32x2 %0, %1, %2;" : "=l"(r) : "l"(a), "l"(b));
    return r;
}
__device__ __forceinline__ float fsigmoid(float x) {
    return __fdividef(1.0f, 1.0f + __expf(-x));
}
__device__ __forceinline__ float ftanh_fast(float x) {
    return 1.0f - __fdividef(2.0f, __expf(2.0f * x) + 1.0f);
}

// ---------- cp.async helpers ----------
__device__ __forceinline__ unsigned int smem_u32(const void* p) {
    return (unsigned int)__cvta_generic_to_shared(p);
}
__device__ __forceinline__ void cp_async16(unsigned int s, const void* g) {
    asm volatile("cp.async.cg.shared.global [%0], [%1], 16;" :: "r"(s), "l"(g));
}
#define CP_COMMIT() asm volatile("cp.async.commit_group;")
#define CP_WAIT1()  asm volatile("cp.async.wait_group 1;")

// ================= x-projection kernel =================
// Both directions per block; thread g holds W_ih rows for dir0/dir1.
// Unrolled by 2 tokens (8 independent FFMA2 chains); pointer-increment stores.
__global__ __launch_bounds__(256, 2)
void xproj_kernel(const float* __restrict__ x,
                  const float* __restrict__ WihF, const float* __restrict__ bihF,
                  const float* __restrict__ bhhF,
                  const float* __restrict__ WihB, const float* __restrict__ bihB,
                  const float* __restrict__ bhhB)
{
    const int g = threadIdx.x;
    __shared__ __align__(16) float sx[XTK * Ix];   // 8 KB

    unsigned long long wf[20], wb[20];
    {
        const float2* wrf = (const float2*)(WihF + (size_t)g * Ix);
        const float2* wrb = (const float2*)(WihB + (size_t)g * Ix);
        #pragma unroll
        for (int j = 0; j < 20; j++) { F2U u; u.f = wrf[j]; wf[j] = u.u; }
        #pragma unroll
        for (int j = 0; j < 20; j++) { F2U u; u.f = wrb[j]; wb[j] = u.u; }
    }
    const float biasF = bihF[g] + bhhF[g];
    const float biasB = bihB[g] + bhhB[g];

    const int tiles_per_b = Tx / XTK;
    const int batch = blockIdx.x / tiles_per_b;
    const int trel  = (blockIdx.x % tiles_per_b) * XTK;

    {
        const float4* xs = (const float4*)(x + ((size_t)batch * Tx + trel) * Ix);
        float4* sd = (float4*)sx;
        #pragma unroll
        for (int i = 0; i < 2; i++) {
            int idx = threadIdx.x + i * 256;
            if (idx < XTK * Ix / 4) sd[idx] = xs[idx];
        }
    }
    __syncthreads();

    float* pF = g_xp[0] + ((size_t)batch * Tx + trel) * Gx + g;
    float* pB = g_xp[1] + ((size_t)batch * Tx + (Tx - 1 - trel)) * Gx + g;
    const ulonglong2* xr = (const ulonglong2*)sx;

    #pragma unroll 1
    for (int k = 0; k < XTK / 2; k++) {
        F2U fa0, fa1, ba0, ba1, fb0, fb1, bb0, bb1;
        fa0.f = make_float2(biasF, 0.0f); fa1.f = make_float2(0.0f, 0.0f);
        ba0.f = make_float2(biasB, 0.0f); ba1.f = make_float2(0.0f, 0.0f);
        fb0 = fa0; fb1 = fa1; bb0 = ba0; bb1 = ba1;
        #pragma unroll
        for (int j = 0; j < 10; j++) {
            const ulonglong2 ua = xr[j];            // token 2k
            const ulonglong2 ub = xr[10 + j];       // token 2k+1
            ffma2(fa0.u, ua.x, wf[2 * j]);  ffma2(fa1.u, ua.y, wf[2 * j + 1]);
            ffma2(ba0.u, ua.x, wb[2 * j]);  ffma2(ba1.u, ua.y, wb[2 * j + 1]);
            ffma2(fb0.u, ub.x, wf[2 * j]);  ffma2(fb1.u, ub.y, wf[2 * j + 1]);
            ffma2(bb0.u, ub.x, wb[2 * j]);  ffma2(bb1.u, ub.y, wb[2 * j + 1]);
        }
        xr += 20;
        F2U s;
        s.u = fadd2(fa0.u, fa1.u); pF[0]   = s.f.x + s.f.y;
        s.u = fadd2(fb0.u, fb1.u); pF[Gx]  = s.f.x + s.f.y;
        s.u = fadd2(ba0.u, ba1.u); pB[0]   = s.f.x + s.f.y;
        s.u = fadd2(bb0.u, bb1.u); pB[-Gx] = s.f.x + s.f.y;
        pF += 2 * Gx;
        pB -= 2 * Gx;
    }
}

// ================= recurrent LSTM kernel =================
// 128 direction-pure blocks; block = 4 sequences of one direction, 256 threads.
// Thread g: gate g for all 4 sequences (one W_hh row in regs). Single wave.
// cp.async pipeline (R3-proven): top of chunk ck issues prefetch for ck+1,
// commits, then wait_group 1 -> waits chunk ck's group, leaves ck+1 in flight.
__global__ __launch_bounds__(256, 1)
void lstm_kernel(const float* __restrict__ Whh_f, const float* __restrict__ Whh_b)
{
    const int dir   = blockIdx.x >> 6;          // blocks 0..63 fwd, 64..127 bwd
    const int bbase = (blockIdx.x & 63) * 4;    // batches bbase..bbase+3

    const float* Whh = dir ? Whh_b : Whh_f;
    float* hout = g_h[dir];
    const float* xpd = g_xp[dir];

    const int g = threadIdx.x;
    const int region = g >> 6;     // warp-uniform gate type (2 = tanh)
    const int us  = g >> 6;        // phase-2: seq index
    const int uix = g & 63;        // phase-2: h index

    __shared__ __align__(16) float sxp[4][2][RCH * Gx];  // 32 KB
    __shared__ __align__(16) float sh[4][Hx];            // 1 KB
    __shared__ float sgates[4][Gx];                      // 4 KB

    // W_hh row (64 floats = 32 f32x2) in registers, shared by all 4 sequences
    unsigned long long whh[32];
    {
        const float2* wr = (const float2*)(Whh + (size_t)g * Hx);
        #pragma unroll
        for (int j = 0; j < 32; j++) { F2U u; u.f = wr[j]; whh[j] = u.u; }
    }

    sh[us][uix] = 0.0f;
    float c = 0.0f;

    // per-thread cp.async slice: seq us, 64B starting at uix*64
    const char* xsrc = (const char*)(xpd + (size_t)(bbase + us) * Tx * Gx) + uix * 64;
    const unsigned int sdst0 = smem_u32(&sxp[us][0][0]) + uix * 64;
    const unsigned int sdst1 = smem_u32(&sxp[us][1][0]) + uix * 64;
    const int CHBYTES = RCH * Gx * 4;   // 4096

    // h output pointer for this thread's (seq, idx); stride ±64 per step
    float* hptr = hout + ((size_t)(bbase + us) * Tx + (dir ? (Tx - 1) : 0)) * Hx + uix;
    const ptrdiff_t hstep = dir ? -Hx : Hx;

    // prefetch chunk 0 into buffer 0
    {
        #pragma unroll
        for (int i = 0; i < 4; i++) cp_async16(sdst0 + i * 16, xsrc + i * 16);
        CP_COMMIT();
    }

    const int NCH = Tx / RCH;
    for (int ck = 0; ck < NCH; ck++) {
        // prefetch next chunk into the other buffer; commit (possibly empty group)
        if (ck + 1 < NCH) {
            const unsigned int sdst = ((ck + 1) & 1) ? sdst1 : sdst0;
            const char* gsrc = xsrc + (size_t)(ck + 1) * CHBYTES;
            #pragma unroll
            for (int i = 0; i < 4; i++) cp_async16(sdst + i * 16, gsrc + i * 16);
        }
        CP_COMMIT();
        CP_WAIT1();          // waits for chunk ck's group; chunk ck+1 stays in flight
        __syncthreads();     // also covers sh init (ck=0) / prior-step writes

        const float* xb0 = sxp[0][ck & 1];
        const float* xb1 = sxp[1][ck & 1];
        const float* xb2 = sxp[2][ck & 1];
        const float* xb3 = sxp[3][ck & 1];

        #pragma unroll 1
        for (int si = 0; si < RCH; si++) {
            // ---- phase 1: gate g for all 4 sequences ----
            const float xv0 = xb0[si * Gx + g];
            const float xv1 = xb1[si * Gx + g];
            const float xv2 = xb2[si * Gx + g];
            const float xv3 = xb3[si * Gx + g];

            F2U a0[4], a1[4];
            a0[0].f = make_float2(xv0, 0.0f);
            a0[1].f = make_float2(xv1, 0.0f);
            a0[2].f = make_float2(xv2, 0.0f);
            a0[3].f = make_float2(xv3, 0.0f);
            a1[0].f = make_float2(0.0f, 0.0f);
            a1[1] = a1[0]; a1[2] = a1[0]; a1[3] = a1[0];

            #pragma unroll
            for (int k = 0; k < 16; k++) {
                const unsigned long long w0 = whh[2 * k];
                const unsigned long long w1 = whh[2 * k + 1];
                #pragma unroll
                for (int ss = 0; ss < 4; ss++) {
                    const ulonglong2 u = ((const ulonglong2*)sh[ss])[k];
                    ffma2(a0[ss].u, u.x, w0);
                    ffma2(a1[ss].u, u.y, w1);
                }
            }
            #pragma unroll
            for (int ss = 0; ss < 4; ss++) {
                F2U s; s.u = fadd2(a0[ss].u, a1[ss].u);
                const float v = s.f.x + s.f.y;
                sgates[ss][g] = (region == 2) ? ftanh_fast(v) : fsigmoid(v);
            }
            __syncthreads();

            // ---- phase 2: exact c/h update, thread = (us, uix) ----
            {
                const float ig = sgates[us][uix];
                const float fg = sgates[us][64 + uix];
                const float gg = sgates[us][128 + uix];
                const float og = sgates[us][192 + uix];
                c = fg * c + ig * gg;
                const float h = og * ftanh_fast(c);
                sh[us][uix] = h;
                *hptr = h;
                hptr += hstep;
            }
            if (si < RCH - 1) __syncthreads();
            // (chunk-closing barrier is the one at the top of the next iteration)
        }
    }
}

// ================= MLP head kernel =================
// 2 lanes per token (hf/hb halves), shfl-combine per output unit.
__global__ __launch_bounds__(256, 2)
void head_kernel(const float* __restrict__ W1, const float* __restrict__ b1,
                 const float* __restrict__ W2, const float* __restrict__ b2,
                 float* __restrict__ out)
{
    __shared__ __align__(16) float sW1[64 * 128];  // 32 KB
    __shared__ float sb1[64];
    __shared__ float sW2[64];

    const int tid = threadIdx.x;
    for (int i = tid; i < 64 * 128 / 4; i += 256)
        ((float4*)sW1)[i] = ((const float4*)W1)[i];
    if (tid < 64) { sb1[tid] = b1[tid]; sW2[tid] = W2[tid]; }
    __syncthreads();
    const float bias2 = b2[0];

    const size_t tok = (size_t)blockIdx.x * 128 + (tid >> 1);
    const int hsel = tid & 1;

    unsigned long long hreg[32];
    {
        const ulonglong2* hv = (const ulonglong2*)(g_h[hsel] + tok * Hx);
        #pragma unroll
        for (int j = 0; j < 16; j++) {
            ulonglong2 u = hv[j];
            hreg[2 * j] = u.x; hreg[2 * j + 1] = u.y;
        }
    }

    float acc = bias2;
    #pragma unroll 4
    for (int o = 0; o < 64; o++) {
        const unsigned long long* w =
            (const unsigned long long*)(sW1 + o * 128 + hsel * 64);
        F2U a0, a1, a2, a3;
        a0.f = make_float2(0.0f, 0.0f);
        a1 = a0; a2 = a0; a3 = a0;
        #pragma unroll
        for (int j = 0; j < 8; j++) {
            ffma2(a0.u, hreg[j],      w[j]);
            ffma2(a1.u, hreg[8 + j],  w[8 + j]);
            ffma2(a2.u, hreg[16 + j], w[16 + j]);
            ffma2(a3.u, hreg[24 + j], w[24 + j]);
        }
        F2U s; s.u = fadd2(fadd2(a0.u, a1.u), fadd2(a2.u, a3.u));
        float v = s.f.x + s.f.y;
        v += __shfl_xor_sync(0xffffffffu, v, 1);
        const float z = fmaxf(v + sb1[o], 0.0f);
        acc = fmaf(z, sW2[o], acc);
    }
    if (hsel == 0) out[tok] = fsigmoid(acc);
}

// ================= launch =================
extern "C" void kernel_launch(void* const* d_in, const int* in_sizes, int n_in,
                              void* d_out, int out_size)
{
    const float* x     = (const float*)d_in[0];
    const float* Wih_f = (const float*)d_in[1];
    const float* Whh_f = (const float*)d_in[2];
    const float* bih_f = (const float*)d_in[3];
    const float* bhh_f = (const float*)d_in[4];
    const float* Wih_b = (const float*)d_in[5];
    const float* Whh_b = (const float*)d_in[6];
    const float* bih_b = (const float*)d_in[7];
    const float* bhh_b = (const float*)d_in[8];
    const float* W1    = (const float*)d_in[9];
    const float* b1    = (const float*)d_in[10];
    const float* W2    = (const float*)d_in[11];
    const float* b2    = (const float*)d_in[12];
    float* out = (float*)d_out;

    xproj_kernel<<<Bx * (Tx / XTK), 256>>>(x, Wih_f, bih_f, bhh_f, Wih_b, bih_b, bhh_b);
    lstm_kernel<<<128, 256>>>(Whh_f, Whh_b);   // 128 blocks x 4 sequences, single wave
    head_kernel<<<(Bx * Tx) / 128, 256>>>(W1, b1, W2, b2, out);
}

// round 6
// speedup vs baseline: 1.0704x; 1.0704x over previous
#include <cuda_runtime.h>
#include <cstdint>

// Problem constants
#define Bx 256
#define Tx 3000
#define Ix 40
#define Hx 64
#define Gx 256        // 4*H gates
#define RCH 4         // recurrent x_proj chunk steps (3000 % 4 == 0 -> 750 chunks)
#define XTK 50        // xproj tokens per block tile (3000 % 50 == 0)

// Scratch (allocation-free rule: __device__ globals)
__device__ float g_h[2][(size_t)Bx * Tx * Hx];    // per-direction hidden outputs
__device__ float g_xp[2][(size_t)Bx * Tx * Gx];   // input projections (+biases); dir1 time-reversed

// ---------- packed f32x2 helpers ----------
union F2U { float2 f; unsigned long long u; };

__device__ __forceinline__ void ffma2(unsigned long long& acc,
                                      unsigned long long a,
                                      unsigned long long b) {
    asm("fma.rn.f32x2 %0, %1, %2, %0;" : "+l"(acc) : "l"(a), "l"(b));
}
__device__ __forceinline__ unsigned long long fadd2(unsigned long long a, unsigned long long b) {
    unsigned long long r;
    asm("add.rn.f32x2 %0, %1, %2;" : "=l"(r) : "l"(a), "l"(b));
    return r;
}
__device__ __forceinline__ float fsigmoid(float x) {
    return __fdividef(1.0f, 1.0f + __expf(-x));
}
__device__ __forceinline__ float ftanh_fast(float x) {
    return 1.0f - __fdividef(2.0f, __expf(2.0f * x) + 1.0f);
}

// ---------- cp.async helpers ----------
__device__ __forceinline__ unsigned int smem_u32(const void* p) {
    return (unsigned int)__cvta_generic_to_shared(p);
}
__device__ __forceinline__ void cp_async16(unsigned int s, const void* g) {
    asm volatile("cp.async.cg.shared.global [%0], [%1], 16;" :: "r"(s), "l"(g));
}
#define CP_COMMIT() asm volatile("cp.async.commit_group;")
#define CP_WAIT1()  asm volatile("cp.async.wait_group 1;")

// team barrier: named barrier per 256-thread team
__device__ __forceinline__ void team_bar(int team) {
    asm volatile("bar.sync %0, 256;" :: "r"(team + 1) : "memory");
}

// ================= x-projection kernel =================
// ONE direction per block (low regs -> 4 blocks/SM). Thread g = gate g.
// 2-token unroll, 4 independent FFMA2 chains, pointer-increment stores.
// dir1 output stored time-reversed.
__global__ __launch_bounds__(256, 4)
void xproj_kernel(const float* __restrict__ x,
                  const float* __restrict__ WihF, const float* __restrict__ bihF,
                  const float* __restrict__ bhhF,
                  const float* __restrict__ WihB, const float* __restrict__ bihB,
                  const float* __restrict__ bhhB)
{
    const int g = threadIdx.x;
    __shared__ __align__(16) float sx[XTK * Ix];   // 8 KB

    const int dir  = blockIdx.x & 1;
    const int rest = blockIdx.x >> 1;
    const int tiles = Tx / XTK;                    // 60
    const int batch = rest / tiles;
    const int trel  = (rest % tiles) * XTK;

    const float* Wih = dir ? WihB : WihF;
    unsigned long long w[20];
    {
        const float2* wr = (const float2*)(Wih + (size_t)g * Ix);
        #pragma unroll
        for (int j = 0; j < 20; j++) { F2U u; u.f = wr[j]; w[j] = u.u; }
    }
    const float bias = dir ? (bihB[g] + bhhB[g]) : (bihF[g] + bhhF[g]);

    {
        const float4* xs = (const float4*)(x + ((size_t)batch * Tx + trel) * Ix);
        float4* sd = (float4*)sx;
        #pragma unroll
        for (int i = 0; i < 2; i++) {
            int idx = threadIdx.x + i * 256;
            if (idx < XTK * Ix / 4) sd[idx] = xs[idx];
        }
    }
    __syncthreads();

    const int t0 = dir ? (Tx - 1 - trel) : trel;
    const ptrdiff_t pstep = dir ? -(ptrdiff_t)Gx : (ptrdiff_t)Gx;
    float* p = g_xp[dir] + ((size_t)batch * Tx + t0) * Gx + g;
    const ulonglong2* xr = (const ulonglong2*)sx;

    #pragma unroll 1
    for (int k = 0; k < XTK / 2; k++) {
        F2U a0, a1, b0, b1;
        a0.f = make_float2(bias, 0.0f); a1.f = make_float2(0.0f, 0.0f);
        b0 = a0; b1 = a1;
        #pragma unroll
        for (int j = 0; j < 10; j++) {
            const ulonglong2 ua = xr[j];        // token 2k
            const ulonglong2 ub = xr[10 + j];   // token 2k+1
            ffma2(a0.u, ua.x, w[2 * j]);  ffma2(a1.u, ua.y, w[2 * j + 1]);
            ffma2(b0.u, ub.x, w[2 * j]);  ffma2(b1.u, ub.y, w[2 * j + 1]);
        }
        xr += 20;
        F2U s;
        s.u = fadd2(a0.u, a1.u); p[0]     = s.f.x + s.f.y;
        s.u = fadd2(b0.u, b1.u); *(p + pstep) = s.f.x + s.f.y;
        p += 2 * pstep;
    }
}

// ================= recurrent LSTM kernel =================
// 128 blocks x 512 threads = 1 block/SM, single balanced wave.
// Block = 2 independent TEAMS of 256 threads (named barriers only);
// team = 2 sequences of one direction; thread g = gate g for both seqs.
// Teams overlap each other's barrier/latency stalls on the same SM.
__global__ __launch_bounds__(512, 1)
void lstm_kernel(const float* __restrict__ Whh_f, const float* __restrict__ Whh_b)
{
    const int dir   = blockIdx.x >> 6;          // 0..63 fwd, 64..127 bwd
    const int bbase = (blockIdx.x & 63) * 4;    // batches bbase..bbase+3

    const float* Whh = dir ? Whh_b : Whh_f;
    float* hout = g_h[dir];
    const float* xpd = g_xp[dir];

    const int tid  = threadIdx.x;
    const int team = tid >> 8;                  // 0 or 1
    const int g    = tid & 255;                 // gate id within team
    const int lA   = 2 * team;                  // local seq ids of this team
    const int lB   = lA + 1;
    const int region = g >> 6;                  // warp-uniform gate type (2 = tanh)

    __shared__ __align__(16) float sxp[4][2][RCH * Gx];  // 32 KB (per-seq buffers)
    __shared__ __align__(16) float sh[4][Hx];            // 1 KB
    __shared__ float sgates[4][Gx];                      // 4 KB

    // W_hh row (64 floats = 32 f32x2) in registers, shared by team's 2 seqs
    unsigned long long whh[32];
    {
        const float2* wr = (const float2*)(Whh + (size_t)g * Hx);
        #pragma unroll
        for (int j = 0; j < 32; j++) { F2U u; u.f = wr[j]; whh[j] = u.u; }
    }

    if (g < 128) sh[lA + (g >> 6)][g & 63] = 0.0f;  // covers all 4 seqs across teams
    float c = 0.0f;

    // phase-2 assignment (2x redundant within team; benign same-value dup)
    const int us  = lA + ((g >> 6) & 1);   // local seq for update
    const int uix = g & 63;

    // cp.async slice: thread covers seq = lA + (g>>7), 32B at ((g&127)*32)
    const int cseq = lA + (g >> 7);
    const char* xsrc = (const char*)(xpd + (size_t)(bbase + cseq) * Tx * Gx) + (g & 127) * 32;
    const unsigned int sdst0 = smem_u32(&sxp[cseq][0][0]) + (g & 127) * 32;
    const unsigned int sdst1 = smem_u32(&sxp[cseq][1][0]) + (g & 127) * 32;
    const int CHBYTES = RCH * Gx * 4;   // 4096

    // h output pointer for this thread's (us, uix)
    float* hptr = hout + ((size_t)(bbase + us) * Tx + (dir ? (Tx - 1) : 0)) * Hx + uix;
    const ptrdiff_t hstep = dir ? -Hx : Hx;

    // prefetch chunk 0 into buffer 0
    cp_async16(sdst0, xsrc);
    cp_async16(sdst0 + 16, xsrc + 16);
    CP_COMMIT();
    __syncthreads();   // sh init visible to both teams (once)

    const int NCH = Tx / RCH;
    for (int ck = 0; ck < NCH; ck++) {
        // prefetch next chunk, commit, wait for CURRENT chunk, team-barrier
        if (ck + 1 < NCH) {
            const unsigned int sdst = ((ck + 1) & 1) ? sdst1 : sdst0;
            const char* gsrc = xsrc + (size_t)(ck + 1) * CHBYTES;
            cp_async16(sdst, gsrc);
            cp_async16(sdst + 16, gsrc + 16);
        }
        CP_COMMIT();
        CP_WAIT1();          // chunk ck landed; ck+1 in flight
        team_bar(team);      // all team threads' copies + prior phase2 writes visible

        const float* xbA = sxp[lA][ck & 1];
        const float* xbB = sxp[lB][ck & 1];

        #pragma unroll 1
        for (int si = 0; si < RCH; si++) {
            // ---- phase 1: gate g for team's 2 sequences ----
            const float xvA = xbA[si * Gx + g];
            const float xvB = xbB[si * Gx + g];

            F2U aA0, aA1, aB0, aB1;
            aA0.f = make_float2(xvA, 0.0f);
            aB0.f = make_float2(xvB, 0.0f);
            aA1.f = make_float2(0.0f, 0.0f);
            aB1 = aA1;

            const ulonglong2* hA = (const ulonglong2*)sh[lA];  // LDS.128 broadcast
            const ulonglong2* hB = (const ulonglong2*)sh[lB];
            #pragma unroll
            for (int k = 0; k < 16; k++) {
                const unsigned long long w0 = whh[2 * k];
                const unsigned long long w1 = whh[2 * k + 1];
                const ulonglong2 ua = hA[k];
                const ulonglong2 ub = hB[k];
                ffma2(aA0.u, ua.x, w0);
                ffma2(aA1.u, ua.y, w1);
                ffma2(aB0.u, ub.x, w0);
                ffma2(aB1.u, ub.y, w1);
            }
            F2U sA; sA.u = fadd2(aA0.u, aA1.u);
            F2U sB; sB.u = fadd2(aB0.u, aB1.u);
            const float vA = sA.f.x + sA.f.y;
            const float vB = sB.f.x + sB.f.y;

            if (region == 2) {
                sgates[lA][g] = ftanh_fast(vA);
                sgates[lB][g] = ftanh_fast(vB);
            } else {
                sgates[lA][g] = fsigmoid(vA);
                sgates[lB][g] = fsigmoid(vB);
            }
            team_bar(team);

            // ---- phase 2: c/h update for (us, uix) ----
            {
                const float ig = sgates[us][uix];
                const float fg = sgates[us][64 + uix];
                const float gg = sgates[us][128 + uix];
                const float og = sgates[us][192 + uix];
                c = fg * c + ig * gg;
                const float h = og * ftanh_fast(c);
                sh[us][uix] = h;
                if (g < 128) { *hptr = h; hptr += hstep; }
                else { hptr += hstep; }   // keep pointer consistent (unused)
            }
            if (si < RCH - 1) team_bar(team);
            // (chunk-closing sync is the team_bar at top of next iteration)
        }
    }
}

// ================= MLP head kernel =================
// 2 lanes per token (hf/hb halves), shfl-combine per output unit.
__global__ __launch_bounds__(256, 2)
void head_kernel(const float* __restrict__ W1, const float* __restrict__ b1,
                 const float* __restrict__ W2, const float* __restrict__ b2,
                 float* __restrict__ out)
{
    __shared__ __align__(16) float sW1[64 * 128];  // 32 KB
    __shared__ float sb1[64];
    __shared__ float sW2[64];

    const int tid = threadIdx.x;
    for (int i = tid; i < 64 * 128 / 4; i += 256)
        ((float4*)sW1)[i] = ((const float4*)W1)[i];
    if (tid < 64) { sb1[tid] = b1[tid]; sW2[tid] = W2[tid]; }
    __syncthreads();
    const float bias2 = b2[0];

    const size_t tok = (size_t)blockIdx.x * 128 + (tid >> 1);
    const int hsel = tid & 1;

    unsigned long long hreg[32];
    {
        const ulonglong2* hv = (const ulonglong2*)(g_h[hsel] + tok * Hx);
        #pragma unroll
        for (int j = 0; j < 16; j++) {
            ulonglong2 u = hv[j];
            hreg[2 * j] = u.x; hreg[2 * j + 1] = u.y;
        }
    }

    float acc = bias2;
    #pragma unroll 4
    for (int o = 0; o < 64; o++) {
        const unsigned long long* w =
            (const unsigned long long*)(sW1 + o * 128 + hsel * 64);
        F2U a0, a1, a2, a3;
        a0.f = make_float2(0.0f, 0.0f);
        a1 = a0; a2 = a0; a3 = a0;
        #pragma unroll
        for (int j = 0; j < 8; j++) {
            ffma2(a0.u, hreg[j],      w[j]);
            ffma2(a1.u, hreg[8 + j],  w[8 + j]);
            ffma2(a2.u, hreg[16 + j], w[16 + j]);
            ffma2(a3.u, hreg[24 + j], w[24 + j]);
        }
        F2U s; s.u = fadd2(fadd2(a0.u, a1.u), fadd2(a2.u, a3.u));
        float v = s.f.x + s.f.y;
        v += __shfl_xor_sync(0xffffffffu, v, 1);
        const float z = fmaxf(v + sb1[o], 0.0f);
        acc = fmaf(z, sW2[o], acc);
    }
    if (hsel == 0) out[tok] = fsigmoid(acc);
}

// ================= launch =================
extern "C" void kernel_launch(void* const* d_in, const int* in_sizes, int n_in,
                              void* d_out, int out_size)
{
    const float* x     = (const float*)d_in[0];
    const float* Wih_f = (const float*)d_in[1];
    const float* Whh_f = (const float*)d_in[2];
    const float* bih_f = (const float*)d_in[3];
    const float* bhh_f = (const float*)d_in[4];
    const float* Wih_b = (const float*)d_in[5];
    const float* Whh_b = (const float*)d_in[6];
    const float* bih_b = (const float*)d_in[7];
    const float* bhh_b = (const float*)d_in[8];
    const float* W1    = (const float*)d_in[9];
    const float* b1    = (const float*)d_in[10];
    const float* W2    = (const float*)d_in[11];
    const float* b2    = (const float*)d_in[12];
    float* out = (float*)d_out;

    xproj_kernel<<<2 * Bx * (Tx / XTK), 256>>>(x, Wih_f, bih_f, bhh_f, Wih_b, bih_b, bhh_b);
    lstm_kernel<<<128, 512>>>(Whh_f, Whh_b);   // 2 teams x 2 seqs per block, single wave
    head_kernel<<<(Bx * Tx) / 128, 256>>>(W1, b1, W2, b2, out);
}